// round 10
// baseline (speedup 1.0000x reference)
#include <cuda_runtime.h>
#include <cuda_bf16.h>
#include <cstdint>

static constexpr int B = 16, H = 256, W = 256;
static constexpr int CIN0 = 3, CMID = 16, COUT = 64;
static constexpr float BN_EPS = 1e-5f;

// h1/h2: channels-last [b][y][x][ci], each elem packed (bf16_hi<<16)|bf16_lo
__device__ uint32_t g_h1[(size_t)B * H * W * CMID];
__device__ uint32_t g_h2[(size_t)B * H * W * CMID];
// conv3 output scratch: channels-last [b][y][x][co], fp32
__device__ float g_h3[(size_t)B * H * W * COUT];
__device__ float g_stats[2 * COUT];
__device__ float g_scale[COUT];
__device__ float g_shift[COUT];

// ---- helpers ---------------------------------------------------------------
__device__ __forceinline__ uint32_t smem_u32(const void* p) {
    uint32_t a;
    asm("{ .reg .u64 t; cvta.to.shared.u64 t, %1; cvt.u32.u64 %0, t; }"
        : "=r"(a) : "l"(p));
    return a;
}
__device__ __forceinline__ void sts64(uint32_t a, uint32_t x, uint32_t y) {
    asm volatile("st.shared.v2.u32 [%0], {%1,%2};" :: "r"(a), "r"(x), "r"(y));
}
__device__ __forceinline__ void sts16(uint32_t a, uint16_t v) {
    asm volatile("st.shared.u16 [%0], %1;" :: "r"(a), "h"(v));
}
__device__ __forceinline__ uint32_t lds32(uint32_t a) {
    uint32_t v;
    asm volatile("ld.shared.b32 %0, [%1];" : "=r"(v) : "r"(a));
    return v;
}
__device__ __forceinline__ uint32_t packhl(float v) {
    __nv_bfloat16 h = __float2bfloat16_rn(v);
    float lo = v - __bfloat162float(h);
    __nv_bfloat16 l = __float2bfloat16_rn(lo);
    return ((uint32_t)__bfloat16_as_ushort(h) << 16) |
           (uint32_t)__bfloat16_as_ushort(l);
}
// baseline-PTX bf16 tensor-core mma (sm_80+)
__device__ __forceinline__ void mma_bf16(float d[4], const uint32_t a[4],
                                         const uint32_t b[2]) {
    asm volatile(
        "mma.sync.aligned.m16n8k16.row.col.f32.bf16.bf16.f32 "
        "{%0,%1,%2,%3},{%4,%5,%6,%7},{%8,%9},{%0,%1,%2,%3};"
        : "+f"(d[0]), "+f"(d[1]), "+f"(d[2]), "+f"(d[3])
        : "r"(a[0]), "r"(a[1]), "r"(a[2]), "r"(a[3]), "r"(b[0]), "r"(b[1]));
}

// ---- tensor-core 3x3 conv (16 in-ch), split-bf16 3-term --------------------
// Tile: 64 px (M) x CO. A per input row: [64 px][K=48], stride 112 B, hi+lo;
// ring of 4 rows. B per dy: [CO][48], hi+lo. 256 threads, 2 blocks/SM.
static constexpr int ALO   = 7168;
static constexpr int ASLOT = 14336;
static constexpr int BBASE = 4 * ASLOT;         // 57344
static constexpr int NY    = 8;
static constexpr int NT    = 256;

// Input layout [b][y][x][ci16] packed: one uint4x4 (64B) load per x.
__device__ __forceinline__ void stage_load(const uint32_t* in, int b, int yin,
                                           int x0, int tid, uint4 c[4]) {
    c[0] = c[1] = c[2] = c[3] = make_uint4(0, 0, 0, 0);
    if (tid >= 66) return;
    const int xin = x0 - 1 + tid;
    if (xin < 0 || xin >= W) return;
    const uint4* p = reinterpret_cast<const uint4*>(
        in + (((size_t)b * H + yin) * W + xin) * 16);
    c[0] = p[0]; c[1] = p[1]; c[2] = p[2]; c[3] = p[3];
}
__device__ __forceinline__ void stage_store(uint32_t s32, int yin, int tid,
                                            const uint4 c[4]) {
    if (tid >= 66) return;
    const int xl = tid;
    const uint32_t Ah = s32 + (uint32_t)(yin & 3) * ASLOT;
    #pragma unroll
    for (int cig = 0; cig < 4; ++cig) {
        const uint32_t h0 = __byte_perm(c[cig].x, c[cig].y, 0x7632);
        const uint32_t h1 = __byte_perm(c[cig].z, c[cig].w, 0x7632);
        const uint32_t l0 = __byte_perm(c[cig].x, c[cig].y, 0x5410);
        const uint32_t l1 = __byte_perm(c[cig].z, c[cig].w, 0x5410);
        #pragma unroll
        for (int dx = 0; dx < 3; ++dx) {
            const int r = xl - dx;
            if (r < 0 || r >= 64) continue;
            const uint32_t off = (uint32_t)(r * 112 + (dx * 16 + cig * 4) * 2);
            sts64(Ah + off, h0, h1);
            sts64(Ah + ALO + off, l0, l1);
        }
    }
}

// Warp grid WM x WN, per-warp fragments MF x NF.
// WM*MF*16 == 64, WN*NF*8 == CO, WM*WN == 8 (256 threads).
// Output: channels-last [b][y][x][CO]; OUTF32 ? fp32 : packed hi/lo uint32.
template <int CO, int WM, int WN, int MF, int NF, bool STATS, bool OUTF32>
__global__ void __launch_bounds__(NT, 2)
conv_mma(const uint32_t* __restrict__ in, const float* __restrict__ wgt,
         void* __restrict__ outv) {
    static_assert(WM * MF * 16 == 64 && WN * NF * 8 == CO && WM * WN == 8, "");
    constexpr int BLO  = CO * 112;
    constexpr int BDY  = 2 * BLO;
    constexpr int SOFF = BBASE + 3 * BDY;

    extern __shared__ char sm[];
    const uint32_t s32 = smem_u32(sm);
    float* sstats = (float*)(sm + SOFF);
    const int tid = threadIdx.x, wid = tid >> 5, lid = tid & 31;
    const int g = lid >> 2, tig = lid & 3;
    int bid = blockIdx.x;
    const int xs = bid & 3, ys = (bid >> 2) & 31, b = bid >> 7;
    const int x0 = xs * 64, y0 = ys * NY;

    if (STATS && tid < 128) sstats[tid] = 0.f;
    for (int i = tid; i < CO * CMID * 9; i += NT) {      // weights -> B tiles
        const int dx = i % 3; int t = i / 3;
        const int dy = t % 3; t /= 3;
        const int ci = t & 15, co = t >> 4;
        const float v = wgt[((co * CMID + ci) * 3 + dy) * 3 + dx];
        __nv_bfloat16 h = __float2bfloat16_rn(v);
        __nv_bfloat16 l = __float2bfloat16_rn(v - __bfloat162float(h));
        const uint32_t a = s32 + BBASE + dy * BDY + co * 112 + (dx * 16 + ci) * 2;
        sts16(a, (uint16_t)__bfloat16_as_ushort(h));
        sts16(a + BLO, (uint16_t)__bfloat16_as_ushort(l));
    }
    {   // prologue: rows y0-1, y0, y0+1
        uint4 pv[4];
        if (y0 > 0) {
            stage_load(in, b, y0 - 1, x0, tid, pv);
            stage_store(s32, y0 - 1, tid, pv);
        }
        stage_load(in, b, y0, x0, tid, pv);
        stage_store(s32, y0, tid, pv);
        stage_load(in, b, y0 + 1, x0, tid, pv);
        stage_store(s32, y0 + 1, tid, pv);
    }
    __syncthreads();

    const int wm = wid % WM, wn = wid / WM;
    float sacc[NF][2] = {}, qacc[NF][2] = {};

    for (int i = 0; i < NY; ++i) {
        const int y = y0 + i;
        const bool have = (y + 2 < H);
        uint4 pf[4];
        if (have) stage_load(in, b, y + 2, x0, tid, pf);  // LDG early

        float acc[MF][NF][4];
        #pragma unroll
        for (int mf = 0; mf < MF; ++mf)
            #pragma unroll
            for (int nf = 0; nf < NF; ++nf)
                #pragma unroll
                for (int r = 0; r < 4; ++r) acc[mf][nf][r] = 0.f;

        #pragma unroll
        for (int dy = 0; dy < 3; ++dy) {
            const int yin = y - 1 + dy;
            if (yin < 0 || yin >= H) continue;
            const uint32_t A0 = s32 + (uint32_t)(yin & 3) * ASLOT;
            const uint32_t B0 = s32 + BBASE + dy * BDY;
            #pragma unroll
            for (int ks = 0; ks < 3; ++ks) {
                uint32_t ah[MF][4], al[MF][4], bh[NF][2], bl[NF][2];
                #pragma unroll
                for (int mf = 0; mf < MF; ++mf) {
                    const uint32_t r0 = A0 +
                        (uint32_t)((wm * (MF * 16) + mf * 16 + g) * 112 +
                                   ks * 32 + tig * 4);
                    const uint32_t r1 = r0 + 8 * 112;
                    ah[mf][0] = lds32(r0);        ah[mf][1] = lds32(r1);
                    ah[mf][2] = lds32(r0 + 16);   ah[mf][3] = lds32(r1 + 16);
                    al[mf][0] = lds32(r0 + ALO);  al[mf][1] = lds32(r1 + ALO);
                    al[mf][2] = lds32(r0 + ALO + 16);
                    al[mf][3] = lds32(r1 + ALO + 16);
                }
                #pragma unroll
                for (int nf = 0; nf < NF; ++nf) {
                    const uint32_t c0 = B0 +
                        (uint32_t)((wn * (NF * 8) + nf * 8 + g) * 112 +
                                   ks * 32 + tig * 4);
                    bh[nf][0] = lds32(c0);        bh[nf][1] = lds32(c0 + 16);
                    bl[nf][0] = lds32(c0 + BLO);  bl[nf][1] = lds32(c0 + BLO + 16);
                }
                #pragma unroll
                for (int mf = 0; mf < MF; ++mf)
                    #pragma unroll
                    for (int nf = 0; nf < NF; ++nf) {
                        mma_bf16(acc[mf][nf], ah[mf], bh[nf]);
                        mma_bf16(acc[mf][nf], ah[mf], bl[nf]);
                        mma_bf16(acc[mf][nf], al[mf], bh[nf]);
                    }
            }
        }

        // epilogue: channels-last, (v0,v1) = adjacent co at x; (v2,v3) at x+8
        #pragma unroll
        for (int mf = 0; mf < MF; ++mf) {
            const int x = x0 + wm * (MF * 16) + mf * 16 + g;
            #pragma unroll
            for (int nf = 0; nf < NF; ++nf) {
                const int co = wn * (NF * 8) + nf * 8 + tig * 2;
                const size_t base = (((size_t)b * H + y) * W + x) * CO + co;
                const float v0 = acc[mf][nf][0], v1 = acc[mf][nf][1];
                const float v2 = acc[mf][nf][2], v3 = acc[mf][nf][3];
                if (OUTF32) {
                    float* p = (float*)outv;
                    *reinterpret_cast<float2*>(p + base) = make_float2(v0, v1);
                    *reinterpret_cast<float2*>(p + base + 8 * CO) =
                        make_float2(v2, v3);
                } else {
                    uint32_t* p = (uint32_t*)outv;
                    *reinterpret_cast<uint2*>(p + base) =
                        make_uint2(packhl(v0), packhl(v1));
                    *reinterpret_cast<uint2*>(p + base + 8 * CO) =
                        make_uint2(packhl(v2), packhl(v3));
                }
                if (STATS) {
                    sacc[nf][0] += v0 + v2;
                    sacc[nf][1] += v1 + v3;
                    qacc[nf][0] = fmaf(v0, v0, fmaf(v2, v2, qacc[nf][0]));
                    qacc[nf][1] = fmaf(v1, v1, fmaf(v3, v3, qacc[nf][1]));
                }
            }
        }
        if (have) stage_store(s32, y + 2, tid, pf);  // slot (y+2)&3 disjoint
        __syncthreads();
    }

    if (STATS) {
        #pragma unroll
        for (int nf = 0; nf < NF; ++nf)
            #pragma unroll
            for (int j = 0; j < 2; ++j) {
                float s = sacc[nf][j], q = qacc[nf][j];
                #pragma unroll
                for (int o = 4; o < 32; o <<= 1) {
                    s += __shfl_xor_sync(0xffffffffu, s, o);
                    q += __shfl_xor_sync(0xffffffffu, q, o);
                }
                if (g == 0) {
                    const int c = wn * (NF * 8) + nf * 8 + tig * 2 + j;
                    atomicAdd(&sstats[c], s);
                    atomicAdd(&sstats[COUT + c], q);
                }
            }
        __syncthreads();
        if (tid < 128) atomicAdd(&g_stats[tid], sstats[tid]);
    }
}

// ---- scalar tiled conv (conv1), channels-last packed output ----------------
template <int CI, int CO, int TH, int TW>
__global__ void __launch_bounds__(256, 2)
conv3x3_tile(const float* __restrict__ in, const float* __restrict__ wgt,
             uint32_t* __restrict__ out) {
    constexpr int NTT = 256, NPX = TH * TW / 8, NCG = CO / 8;
    static_assert(NPX * NCG == NTT, "shape");
    constexpr int IH = TH + 2, IW = TW + 2, RS = (IW + 3) & ~3;
    extern __shared__ float fsm[];
    float* s_in = fsm;
    float* s_w  = fsm + CI * IH * RS;

    const int tid = threadIdx.x;
    int bid = blockIdx.x;
    const int tx = bid % (W / TW); bid /= (W / TW);
    const int ty = bid % (H / TH); bid /= (H / TH);
    const int b = bid;

    for (int i = tid; i < CI * 9 * CO; i += NTT) {
        const int k = i / CO, co = i - k * CO, ci = k / 9, t = k - ci * 9;
        s_w[i] = wgt[(co * CI + ci) * 9 + t];
    }
    const float* inb = in + (size_t)b * CI * H * W;
    const int gy0 = ty * TH - 1, gx0 = tx * TW - 1;
    for (int i = tid; i < CI * IH * IW; i += NTT) {
        const int ci = i / (IH * IW);
        int r = i - ci * IH * IW;
        const int y = r / IW, x = r - y * IW;
        const int gy = gy0 + y, gx = gx0 + x;
        float v = 0.f;
        if (gy >= 0 && gy < H && gx >= 0 && gx < W)
            v = inb[(ci * H + gy) * W + gx];
        s_in[(ci * IH + y) * RS + x] = v;
    }
    __syncthreads();

    const int px = tid % NPX, cg = tid / NPX;
    const int py = px / (TW / 8), x0 = (px - py * (TW / 8)) * 8, co0 = cg * 8;
    float acc[8][8];
    #pragma unroll
    for (int i = 0; i < 8; ++i)
        #pragma unroll
        for (int j = 0; j < 8; ++j) acc[i][j] = 0.f;

    #pragma unroll 1
    for (int ci = 0; ci < CI; ++ci)
        #pragma unroll
        for (int dy = 0; dy < 3; ++dy) {
            const float* rp = &s_in[(ci * IH + py + dy) * RS + x0];
            float rr[10];
            const float4 a0 = *reinterpret_cast<const float4*>(rp);
            const float4 a1 = *reinterpret_cast<const float4*>(rp + 4);
            const float2 a2 = *reinterpret_cast<const float2*>(rp + 8);
            rr[0]=a0.x; rr[1]=a0.y; rr[2]=a0.z; rr[3]=a0.w;
            rr[4]=a1.x; rr[5]=a1.y; rr[6]=a1.z; rr[7]=a1.w;
            rr[8]=a2.x; rr[9]=a2.y;
            #pragma unroll
            for (int dx = 0; dx < 3; ++dx) {
                const float* wp = &s_w[(ci * 9 + dy * 3 + dx) * CO + co0];
                const float4 w0 = *reinterpret_cast<const float4*>(wp);
                const float4 w1 = *reinterpret_cast<const float4*>(wp + 4);
                const float wv[8] = {w0.x, w0.y, w0.z, w0.w, w1.x, w1.y, w1.z, w1.w};
                #pragma unroll
                for (int co = 0; co < 8; ++co)
                    #pragma unroll
                    for (int p = 0; p < 8; ++p)
                        acc[co][p] = fmaf(wv[co], rr[p + dx], acc[co][p]);
            }
        }
    // channels-last packed: [b][y][x][ci16], 8 consecutive ci per thread
    const int oy = ty * TH + py, ox = tx * TW + x0;
    #pragma unroll
    for (int p = 0; p < 8; ++p) {
        uint32_t* op = out + (((size_t)b * H + oy) * W + (ox + p)) * CO + co0;
        uint4 ua, ub;
        ua.x = packhl(acc[0][p]); ua.y = packhl(acc[1][p]);
        ua.z = packhl(acc[2][p]); ua.w = packhl(acc[3][p]);
        ub.x = packhl(acc[4][p]); ub.y = packhl(acc[5][p]);
        ub.z = packhl(acc[6][p]); ub.w = packhl(acc[7][p]);
        *reinterpret_cast<uint4*>(op)     = ua;
        *reinterpret_cast<uint4*>(op + 4) = ub;
    }
}

__global__ void zero_stats_kernel() {
    if (threadIdx.x < 2 * COUT) g_stats[threadIdx.x] = 0.f;
}
__global__ void bn_finalize_kernel(const float* __restrict__ gamma,
                                   const float* __restrict__ beta) {
    const int c = threadIdx.x;
    if (c >= COUT) return;
    const float n = (float)B * H * W;
    const float mean = g_stats[c] / n;
    const float var  = g_stats[COUT + c] / n - mean * mean;
    const float sc   = gamma[c] * rsqrtf(var + BN_EPS);
    g_scale[c] = sc;
    g_shift[c] = beta[c] - mean * sc;
}

// channels-last [b][y][x][co] -> NCHW with scale/shift; smem transpose
__global__ void __launch_bounds__(256)
bn_transpose_kernel(const float* __restrict__ src, float* __restrict__ out) {
    __shared__ float t[64 * 65];
    int bid = blockIdx.x;
    const int xs = bid & 3, y = (bid >> 2) & 255, b = bid >> 10;
    const float* sp = src + (((size_t)b * H + y) * W + xs * 64) * 64;
    for (int i = threadIdx.x; i < 1024; i += 256) {      // 4096 floats in
        const float4 v = reinterpret_cast<const float4*>(sp)[i];
        const int x = (i * 4) >> 6, co = (i * 4) & 63;
        t[x * 65 + co]     = v.x;
        t[x * 65 + co + 1] = v.y;
        t[x * 65 + co + 2] = v.z;
        t[x * 65 + co + 3] = v.w;
    }
    __syncthreads();
    for (int j = threadIdx.x; j < 1024; j += 256) {
        const int co = j >> 4, xq = (j & 15) * 4;
        const float sc = g_scale[co], sh = g_shift[co];
        float4 v;
        v.x = fmaf(t[(xq + 0) * 65 + co], sc, sh);
        v.y = fmaf(t[(xq + 1) * 65 + co], sc, sh);
        v.z = fmaf(t[(xq + 2) * 65 + co], sc, sh);
        v.w = fmaf(t[(xq + 3) * 65 + co], sc, sh);
        float* op = out + (((size_t)b * COUT + co) * H + y) * W + xs * 64 + xq;
        *reinterpret_cast<float4*>(op) = v;
    }
}

extern "C" void kernel_launch(void* const* d_in, const int* in_sizes, int n_in,
                              void* d_out, int out_size) {
    (void)in_sizes; (void)n_in; (void)out_size;
    const float* x     = (const float*)d_in[0];
    const float* w1    = (const float*)d_in[1];
    const float* w2    = (const float*)d_in[2];
    const float* w3    = (const float*)d_in[3];
    const float* gamma = (const float*)d_in[4];
    const float* beta  = (const float*)d_in[5];
    float* out = (float*)d_out;

    uint32_t *h1, *h2;
    float* h3;
    cudaGetSymbolAddress((void**)&h1, g_h1);
    cudaGetSymbolAddress((void**)&h2, g_h2);
    cudaGetSymbolAddress((void**)&h3, g_h3);

    auto* k1 = conv3x3_tile<CIN0, CMID, 32, 32>;
    auto* k2 = conv_mma<16, 4, 2, 1, 1, false, false>;   // h1 -> packed h2
    auto* k3 = conv_mma<64, 2, 4, 2, 2, true,  true>;    // h2 -> fp32 h3

    constexpr int SM1 = (CIN0 * 34 * 36 + CIN0 * 9 * CMID) * 4;
    constexpr int SM2 = BBASE + 3 * (2 * 16 * 112) + 512;   //  68,608
    constexpr int SM3 = BBASE + 3 * (2 * 64 * 112) + 512;   // 100,864

    cudaFuncSetAttribute(k1, cudaFuncAttributeMaxDynamicSharedMemorySize, SM1);
    cudaFuncSetAttribute(k2, cudaFuncAttributeMaxDynamicSharedMemorySize, SM2);
    cudaFuncSetAttribute(k3, cudaFuncAttributeMaxDynamicSharedMemorySize, SM3);

    zero_stats_kernel<<<1, 128>>>();
    k1<<<B * (H / 32) * (W / 32), 256, SM1>>>(x, w1, h1);
    k2<<<B * 32 * 4, NT, SM2>>>(h1, w2, h2);
    k3<<<B * 32 * 4, NT, SM3>>>(h2, w3, h3);
    bn_finalize_kernel<<<1, 64>>>(gamma, beta);
    bn_transpose_kernel<<<B * H * 4, 256>>>(h3, out);
}